// round 7
// baseline (speedup 1.0000x reference)
#include <cuda_runtime.h>
#include <cuda_bf16.h>
#include <math.h>

#define BB   512   // batch
#define TT   128   // time steps
#define FF   256   // features
#define HH   512   // hidden
#define KK   3     // fuzzy rules

typedef unsigned long long ull;

// ------------------------------------------------------------------
// Device scratch
// ------------------------------------------------------------------
__device__ float g_xw[(size_t)TT * BB * HH];   // [T][B][H]
__device__ float g_hT[2][(size_t)HH * BB];     // hidden state TRANSPOSED [H][B], ping-pong
__device__ float g_Wxs[FF * HH];               // diag(sigmoid(theta)) @ Wx
__device__ float g_gp[(HH / 2) * 20];          // packed gate params per column-pair

// ------------------------------------------------------------------
// Packed f32x2 helpers
// ------------------------------------------------------------------
__device__ __forceinline__ ull pack2(float x, float y) {
    ull r; asm("mov.b64 %0, {%1, %2};" : "=l"(r) : "f"(x), "f"(y)); return r;
}
__device__ __forceinline__ float2 unpack2(ull v) {
    float2 r; asm("mov.b64 {%0, %1}, %2;" : "=f"(r.x), "=f"(r.y) : "l"(v)); return r;
}
__device__ __forceinline__ ull fma2(ull a, ull b, ull c) {
    ull d; asm("fma.rn.f32x2 %0, %1, %2, %3;" : "=l"(d) : "l"(a), "l"(b), "l"(c)); return d;
}

// ------------------------------------------------------------------
// Prep: fold selector into Wx, emit weights, pack gate params.
// gp per column-pair (cols 2p,2p+1), 20 floats:
//  [0..2]=c0 [3]=b0 [4..6]=inv0 [7..9]=q0 ; [10..12]=c1 [13]=b1 [14..16]=inv1 [17..19]=q1
// ------------------------------------------------------------------
__global__ void prep_kernel(const float* __restrict__ theta,
                            const float* __restrict__ Wx,
                            const float* __restrict__ sigma,
                            const float* __restrict__ cC,
                            const float* __restrict__ qQ,
                            const float* __restrict__ bias,
                            float* __restrict__ out)
{
    int idx = blockIdx.x * blockDim.x + threadIdx.x;
    if (idx < FF * HH) {
        int f = idx >> 9;
        float w = 1.0f / (1.0f + expf(-theta[f]));
        g_Wxs[idx] = w * Wx[idx];
    }
    if (idx < FF) out[BB + idx] = 1.0f / (1.0f + expf(-theta[idx]));
    if (idx < HH / 2) {
        float* gp = g_gp + idx * 20;
        #pragma unroll
        for (int j = 0; j < 2; ++j) {
            int col = idx * 2 + j;
            float* o = gp + j * 10;
            #pragma unroll
            for (int s = 0; s < 3; ++s) {
                float sg = sigma[col * 3 + s];
                o[0 + s] = cC[col * 3 + s];
                o[4 + s] = 1.0f / (2.0f * sg * sg + 1e-8f);
                o[7 + s] = qQ[col * 3 + s];
            }
            o[3] = bias[col];
        }
    }
}

// ------------------------------------------------------------------
// GEMM1 (proven): g_xw[t][b][h] = sum_f x[b][t][f] * Wxs[f][h]
// ------------------------------------------------------------------
__global__ void __launch_bounds__(256) gemm1_kernel(const float* __restrict__ x)
{
    __shared__ float sA[16][130];
    __shared__ float sB[16][128];

    const int tid = threadIdx.x;
    const int m0  = blockIdx.x * 128;
    const int n0  = blockIdx.y * 128;

    const int ar = tid >> 1;
    const int ak = (tid & 1) * 8;
    const int bk = tid >> 4;
    const int bc = (tid & 15) * 8;

    const float* Ag = x     + (size_t)(m0 + ar) * FF + ak;
    const float* Bg = g_Wxs + (size_t)bk * HH + n0 + bc;

    float4 ra0 = *(const float4*)(Ag);
    float4 ra1 = *(const float4*)(Ag + 4);
    float4 rb0 = *(const float4*)(Bg);
    float4 rb1 = *(const float4*)(Bg + 4);

    ull acc[4][8];
    #pragma unroll
    for (int i = 0; i < 4; ++i)
        #pragma unroll
        for (int j = 0; j < 8; ++j) acc[i][j] = 0ull;

    const int ty = tid >> 4;
    const int tx = tid & 15;

    #pragma unroll 1
    for (int kt = 0; kt < FF / 16; ++kt) {
        sA[ak + 0][ar] = ra0.x; sA[ak + 1][ar] = ra0.y;
        sA[ak + 2][ar] = ra0.z; sA[ak + 3][ar] = ra0.w;
        sA[ak + 4][ar] = ra1.x; sA[ak + 5][ar] = ra1.y;
        sA[ak + 6][ar] = ra1.z; sA[ak + 7][ar] = ra1.w;
        *(float4*)&sB[bk][bc]     = rb0;
        *(float4*)&sB[bk][bc + 4] = rb1;
        __syncthreads();

        if (kt < FF / 16 - 1) {
            const float* Ag2 = Ag + (kt + 1) * 16;
            const float* Bg2 = Bg + (size_t)(kt + 1) * 16 * HH;
            ra0 = *(const float4*)(Ag2);
            ra1 = *(const float4*)(Ag2 + 4);
            rb0 = *(const float4*)(Bg2);
            rb1 = *(const float4*)(Bg2 + 4);
        }

        #pragma unroll
        for (int kk = 0; kk < 16; ++kk) {
            ull a2[4];
            #pragma unroll
            for (int i = 0; i < 4; ++i)
                a2[i] = *(const ull*)&sA[kk][ty * 8 + 2 * i];
            float bf[8];
            *(float4*)&bf[0] = *(const float4*)&sB[kk][tx * 8];
            *(float4*)&bf[4] = *(const float4*)&sB[kk][tx * 8 + 4];
            #pragma unroll
            for (int j = 0; j < 8; ++j) {
                ull bbv = pack2(bf[j], bf[j]);
                #pragma unroll
                for (int i = 0; i < 4; ++i)
                    acc[i][j] = fma2(a2[i], bbv, acc[i][j]);
            }
        }
        __syncthreads();
    }

    #pragma unroll
    for (int i = 0; i < 4; ++i) {
        float2 v[8];
        #pragma unroll
        for (int j = 0; j < 8; ++j) v[j] = unpack2(acc[i][j]);
        #pragma unroll
        for (int p = 0; p < 2; ++p) {
            int m = m0 + ty * 8 + 2 * i + p;
            int t = m & (TT - 1);
            int b = m >> 7;
            float* orow = g_xw + ((size_t)t * BB + b) * HH + n0 + tx * 8;
            float4 o0, o1;
            if (p == 0) {
                o0 = make_float4(v[0].x, v[1].x, v[2].x, v[3].x);
                o1 = make_float4(v[4].x, v[5].x, v[6].x, v[7].x);
            } else {
                o0 = make_float4(v[0].y, v[1].y, v[2].y, v[3].y);
                o1 = make_float4(v[4].y, v[5].y, v[6].y, v[7].y);
            }
            *(float4*)(orow)     = o0;
            *(float4*)(orow + 4) = o1;
        }
    }
}

// ------------------------------------------------------------------
// Persistent recurrence kernel v2 (fixed: global column index into sH).
// 128 CTAs x 512 threads, clusters of 8 sharing one 32-row batch tile.
// ------------------------------------------------------------------
#define SRED_ULL 4160   // 4 groups * 1040 (8 rows x stride 130)

__global__ void __launch_bounds__(512, 1) __cluster_dims__(8, 1, 1)
rnn_persistent(const float* __restrict__ Wh)
{
    extern __shared__ float smem[];
    float* sW = smem;                    // [512][64]  Wh slice   (131072 B)
    float* sH = smem + HH * 64;          // [512][32]  h tile     (65536 B)
    ull*   sRed = (ull*)(smem + HH * 64 + HH * 32);   // partials (33280 B)

    const int tid = threadIdx.x;
    const int m0  = (blockIdx.x >> 3) * 32;   // batch tile
    const int n0  = (blockIdx.x & 7) * 64;    // hidden slice

    // ---- GEMM thread mapping: group g (K-split), 4 warps per group ----
    const int g    = tid >> 7;          // 0..3, k in [g*128, g*128+128)
    const int lid  = tid & 127;
    const int w    = lid >> 5;
    const int lane = lid & 31;
    const int mbase = (w & 1) * 16 + (lane & 3) * 4;    // 0..28
    const int nbase = (w >> 1) * 32 + (lane >> 2) * 4;  // 0..60

    // ---- gate/reduce mapping ----
    const int rlid  = tid >> 2;
    const int j8    = (tid & 3) * 2;
    const int rw    = rlid >> 5;
    const int rlane = rlid & 31;
    const int ri    = j8 >> 2;                                   // av half
    const int rm2   = (rw & 1) * 16 + (rlane & 3) * 4 + ri * 2;  // local m pair base
    const int rcol  = (rw >> 1) * 32 + (rlane >> 2) * 4 + (j8 & 3); // local col (even)

    // ---- load Wh slice into smem once ----
    {
        const int n16 = tid & 15;
        const int kr  = tid >> 4;
        #pragma unroll
        for (int i = 0; i < 16; ++i) {
            int k = kr + i * 32;
            *(float4*)&sW[k * 64 + n16 * 4] =
                *(const float4*)&Wh[(size_t)k * HH + n0 + n16 * 4];
        }
    }

    // ---- preload gate params (once) ----
    const int colg = n0 + rcol;          // global col (even)
    const float* gp = g_gp + (size_t)(colg >> 1) * 20;
    float4 p0 = *(const float4*)(gp + 0);
    float4 p1 = *(const float4*)(gp + 4);
    float4 p2 = *(const float4*)(gp + 8);
    float4 p3 = *(const float4*)(gp + 12);
    float4 p4 = *(const float4*)(gp + 16);
    float cc[2][3]  = {{p0.x, p0.y, p0.z}, {p2.z, p2.w, p3.x}};
    float bb2[2]    = {p0.w, p3.y};
    float iv[2][3]  = {{p1.x, p1.y, p1.z}, {p3.z, p3.w, p4.x}};
    float qq[2][3]  = {{p1.w, p2.x, p2.y}, {p4.y, p4.z, p4.w}};

    // staging indices for h tile
    const int smq = tid & 7;             // m quad 0..7
    const int skr = tid >> 3;            // k row 0..63 (step 64)

    const float* ap = sH + mbase;
    const float* bp = sW + nbase;
    const int kbeg = g * 128;

    for (int t = 0; t < TT; ++t) {
        // ---- stage h_t tile into sH[k][m] (k = GLOBAL hidden index) ----
        if (t == 0) {
            const float4 z4 = make_float4(0.f, 0.f, 0.f, 0.f);
            #pragma unroll
            for (int i = 0; i < 8; ++i)
                *(float4*)&sH[(skr + i * 64) * 32 + smq * 4] = z4;
        } else {
            const float* hsrc = g_hT[t & 1];
            #pragma unroll
            for (int i = 0; i < 8; ++i) {
                int k = skr + i * 64;
                *(float4*)&sH[k * 32 + smq * 4] =
                    *(const float4*)&hsrc[(size_t)k * BB + m0 + smq * 4];
            }
        }
        __syncthreads();

        // ---- GEMM: this group's K range, sync-free out of smem ----
        ull acc[2][4];
        #pragma unroll
        for (int i = 0; i < 2; ++i)
            #pragma unroll
            for (int j = 0; j < 4; ++j) acc[i][j] = 0ull;

        #pragma unroll 8
        for (int kk = 0; kk < 128; ++kk) {
            const int k = kbeg + kk;
            ulonglong2 av = *(const ulonglong2*)(ap + k * 32);
            float4     bv = *(const float4*)(bp + k * 64);
            ull b0 = pack2(bv.x, bv.x);
            ull b1 = pack2(bv.y, bv.y);
            ull b2 = pack2(bv.z, bv.z);
            ull b3 = pack2(bv.w, bv.w);
            acc[0][0] = fma2(av.x, b0, acc[0][0]);
            acc[0][1] = fma2(av.x, b1, acc[0][1]);
            acc[0][2] = fma2(av.x, b2, acc[0][2]);
            acc[0][3] = fma2(av.x, b3, acc[0][3]);
            acc[1][0] = fma2(av.y, b0, acc[1][0]);
            acc[1][1] = fma2(av.y, b1, acc[1][1]);
            acc[1][2] = fma2(av.y, b2, acc[1][2]);
            acc[1][3] = fma2(av.y, b3, acc[1][3]);
        }

        // ---- write partials ----
        {
            ull* dst = sRed + g * 1040;
            #pragma unroll
            for (int i = 0; i < 2; ++i)
                #pragma unroll
                for (int j = 0; j < 4; ++j)
                    dst[(i * 4 + j) * 130 + lid] = acc[i][j];
        }
        __syncthreads();

        // ---- reduce 4 partials + fused gate ----
        const float* xwt = g_xw + (size_t)t * (BB * HH);
        float* hnxt = g_hT[(t + 1) & 1];

        float2 z0 = make_float2(0.f, 0.f);
        float2 z1 = make_float2(0.f, 0.f);
        #pragma unroll
        for (int gg = 0; gg < 4; ++gg) {
            const ull* src = sRed + gg * 1040 + j8 * 130 + rlid;
            float2 a = unpack2(src[0]);
            float2 b = unpack2(src[130]);
            z0.x += a.x; z0.y += a.y;
            z1.x += b.x; z1.y += b.y;
        }

        // hcur from sH — FIX: index by GLOBAL column colg, not local rcol
        const int r0 = m0 + rm2;
        float2 h0 = *(const float2*)&sH[(colg + 0) * 32 + rm2];
        float2 h1 = *(const float2*)&sH[(colg + 1) * 32 + rm2];
        float2 xr0 = *(const float2*)&xwt[(size_t)(r0 + 0) * HH + colg];
        float2 xr1 = *(const float2*)&xwt[(size_t)(r0 + 1) * HH + colg];

        float zv[2][2] = {{z0.x, z0.y}, {z1.x, z1.y}};   // [col][m]
        float xv[2][2] = {{xr0.x, xr1.x}, {xr0.y, xr1.y}};
        float hv[2][2] = {{h0.x, h0.y}, {h1.x, h1.y}};
        float hn[2][2];

        #pragma unroll
        for (int j = 0; j < 2; ++j) {
            #pragma unroll
            for (int p = 0; p < 2; ++p) {
                float x  = xv[j][p];
                float z  = zv[j][p] + x + bb2[j];
                float d0 = z - cc[j][0], d1 = z - cc[j][1], d2 = z - cc[j][2];
                float mu0 = __expf(-d0 * d0 * iv[j][0]);
                float mu1 = __expf(-d1 * d1 * iv[j][1]);
                float mu2 = __expf(-d2 * d2 * iv[j][2]);
                float num = mu0 * qq[j][0] + mu1 * qq[j][1] + mu2 * qq[j][2];
                float den = mu0 + mu1 + mu2 + 1e-8f;
                float gt  = 1.0f / (1.0f + __expf(-num / den));
                float ex  = __expf(-2.0f * x);
                float ni  = (1.0f - ex) / (1.0f + ex);
                hn[j][p] = (1.0f - gt) * hv[j][p] + gt * ni;
            }
            *(float2*)&hnxt[(size_t)(colg + j) * BB + r0] = make_float2(hn[j][0], hn[j][1]);
        }

        // ---- publish + cluster-wide step barrier ----
        asm volatile("fence.acq_rel.cluster;" ::: "memory");
        asm volatile("barrier.cluster.arrive.aligned;" ::: "memory");
        asm volatile("barrier.cluster.wait.aligned;"   ::: "memory");
    }
}

// ------------------------------------------------------------------
// Final: logits[b] = h_T[:,b] . Wc + bc ; h_T = g_hT[0], layout [H][B].
// ------------------------------------------------------------------
__global__ void __launch_bounds__(256) final_kernel(const float* __restrict__ Wc,
                                                    const float* __restrict__ bc,
                                                    float* __restrict__ out)
{
    __shared__ float sP[8][32];
    const int bl = threadIdx.x & 31;
    const int hg = threadIdx.x >> 5;
    const int b  = blockIdx.x * 32 + bl;
    const float* hT = g_hT[0];
    float s = 0.0f;
    #pragma unroll 8
    for (int i = 0; i < 64; ++i) {
        int h = hg * 64 + i;
        s += hT[(size_t)h * BB + b] * Wc[h];
    }
    sP[hg][bl] = s;
    __syncthreads();
    if (hg == 0) {
        float r = sP[0][bl] + sP[1][bl] + sP[2][bl] + sP[3][bl]
                + sP[4][bl] + sP[5][bl] + sP[6][bl] + sP[7][bl];
        out[b] = r + bc[0];
    }
}

// ------------------------------------------------------------------
// Launch
// ------------------------------------------------------------------
extern "C" void kernel_launch(void* const* d_in, const int* in_sizes, int n_in,
                              void* d_out, int out_size)
{
    const float* x     = (const float*)d_in[0];
    const float* theta = (const float*)d_in[1];
    const float* Wx    = (const float*)d_in[2];
    const float* Wh    = (const float*)d_in[3];
    const float* bias  = (const float*)d_in[4];
    const float* c     = (const float*)d_in[5];
    const float* sigma = (const float*)d_in[6];
    const float* q     = (const float*)d_in[7];
    const float* Wc    = (const float*)d_in[8];
    const float* bc    = (const float*)d_in[9];
    float* out = (float*)d_out;

    const int smem_bytes = (HH * 64 + HH * 32) * sizeof(float) + SRED_ULL * sizeof(ull);
    cudaFuncSetAttribute(rnn_persistent,
                         cudaFuncAttributeMaxDynamicSharedMemorySize, smem_bytes);

    prep_kernel<<<(FF * HH + 255) / 256, 256>>>(theta, Wx, sigma, c, q, bias, out);
    gemm1_kernel<<<dim3((BB * TT) / 128, HH / 128), 256>>>(x);
    rnn_persistent<<<128, 512, smem_bytes>>>(Wh);
    final_kernel<<<16, 256>>>(Wc, bc, out);
}

// round 8
// speedup vs baseline: 1.5562x; 1.5562x over previous
#include <cuda_runtime.h>
#include <cuda_bf16.h>
#include <math.h>

#define BB   512   // batch
#define TT   128   // time steps
#define FF   256   // features
#define HH   512   // hidden
#define KK   3     // fuzzy rules

typedef unsigned long long ull;

// ------------------------------------------------------------------
// Device scratch
// ------------------------------------------------------------------
__device__ float g_xw[(size_t)TT * BB * HH];   // [T][B][H]
__device__ float g_h2[2][(size_t)BB * HH];     // ping-pong hidden state [B][H]
__device__ float g_Wxs[FF * HH];               // diag(sigmoid(theta)) @ Wx
__device__ float g_gp[(HH / 2) * 20];          // packed gate params per column-pair

// ------------------------------------------------------------------
// Packed f32x2 helpers
// ------------------------------------------------------------------
__device__ __forceinline__ ull pack2(float x, float y) {
    ull r; asm("mov.b64 %0, {%1, %2};" : "=l"(r) : "f"(x), "f"(y)); return r;
}
__device__ __forceinline__ float2 unpack2(ull v) {
    float2 r; asm("mov.b64 {%0, %1}, %2;" : "=f"(r.x), "=f"(r.y) : "l"(v)); return r;
}
__device__ __forceinline__ ull fma2(ull a, ull b, ull c) {
    ull d; asm("fma.rn.f32x2 %0, %1, %2, %3;" : "=l"(d) : "l"(a), "l"(b), "l"(c)); return d;
}

// ------------------------------------------------------------------
// Prep: zero h0, fold selector into Wx, emit weights, pack gate params.
// gp per column-pair (cols 2p,2p+1), 20 floats:
//  [0..2]=c0 [3]=b0 [4..6]=inv0 [7..9]=q0 ; [10..12]=c1 [13]=b1 [14..16]=inv1 [17..19]=q1
// ------------------------------------------------------------------
__global__ void prep_kernel(const float* __restrict__ theta,
                            const float* __restrict__ Wx,
                            const float* __restrict__ sigma,
                            const float* __restrict__ cC,
                            const float* __restrict__ qQ,
                            const float* __restrict__ bias,
                            float* __restrict__ out)
{
    int idx = blockIdx.x * blockDim.x + threadIdx.x;
    if (idx < BB * HH) g_h2[0][idx] = 0.0f;
    if (idx < FF * HH) {
        int f = idx >> 9;
        float w = 1.0f / (1.0f + expf(-theta[f]));
        g_Wxs[idx] = w * Wx[idx];
    }
    if (idx < FF) out[BB + idx] = 1.0f / (1.0f + expf(-theta[idx]));
    if (idx < HH / 2) {
        float* gp = g_gp + idx * 20;
        #pragma unroll
        for (int j = 0; j < 2; ++j) {
            int col = idx * 2 + j;
            float* o = gp + j * 10;
            #pragma unroll
            for (int s = 0; s < 3; ++s) {
                float sg = sigma[col * 3 + s];
                o[0 + s] = cC[col * 3 + s];
                o[4 + s] = 1.0f / (2.0f * sg * sg + 1e-8f);
                o[7 + s] = qQ[col * 3 + s];
            }
            o[3] = bias[col];
        }
    }
}

// ------------------------------------------------------------------
// GEMM1 (proven): g_xw[t][b][h] = sum_f x[b][t][f] * Wxs[f][h]
// ------------------------------------------------------------------
__global__ void __launch_bounds__(256) gemm1_kernel(const float* __restrict__ x)
{
    __shared__ float sA[16][130];
    __shared__ float sB[16][128];

    const int tid = threadIdx.x;
    const int m0  = blockIdx.x * 128;
    const int n0  = blockIdx.y * 128;

    const int ar = tid >> 1;
    const int ak = (tid & 1) * 8;
    const int bk = tid >> 4;
    const int bc = (tid & 15) * 8;

    const float* Ag = x     + (size_t)(m0 + ar) * FF + ak;
    const float* Bg = g_Wxs + (size_t)bk * HH + n0 + bc;

    float4 ra0 = *(const float4*)(Ag);
    float4 ra1 = *(const float4*)(Ag + 4);
    float4 rb0 = *(const float4*)(Bg);
    float4 rb1 = *(const float4*)(Bg + 4);

    ull acc[4][8];
    #pragma unroll
    for (int i = 0; i < 4; ++i)
        #pragma unroll
        for (int j = 0; j < 8; ++j) acc[i][j] = 0ull;

    const int ty = tid >> 4;
    const int tx = tid & 15;

    #pragma unroll 1
    for (int kt = 0; kt < FF / 16; ++kt) {
        sA[ak + 0][ar] = ra0.x; sA[ak + 1][ar] = ra0.y;
        sA[ak + 2][ar] = ra0.z; sA[ak + 3][ar] = ra0.w;
        sA[ak + 4][ar] = ra1.x; sA[ak + 5][ar] = ra1.y;
        sA[ak + 6][ar] = ra1.z; sA[ak + 7][ar] = ra1.w;
        *(float4*)&sB[bk][bc]     = rb0;
        *(float4*)&sB[bk][bc + 4] = rb1;
        __syncthreads();

        if (kt < FF / 16 - 1) {
            const float* Ag2 = Ag + (kt + 1) * 16;
            const float* Bg2 = Bg + (size_t)(kt + 1) * 16 * HH;
            ra0 = *(const float4*)(Ag2);
            ra1 = *(const float4*)(Ag2 + 4);
            rb0 = *(const float4*)(Bg2);
            rb1 = *(const float4*)(Bg2 + 4);
        }

        #pragma unroll
        for (int kk = 0; kk < 16; ++kk) {
            ull a2[4];
            #pragma unroll
            for (int i = 0; i < 4; ++i)
                a2[i] = *(const ull*)&sA[kk][ty * 8 + 2 * i];
            float bf[8];
            *(float4*)&bf[0] = *(const float4*)&sB[kk][tx * 8];
            *(float4*)&bf[4] = *(const float4*)&sB[kk][tx * 8 + 4];
            #pragma unroll
            for (int j = 0; j < 8; ++j) {
                ull bbv = pack2(bf[j], bf[j]);
                #pragma unroll
                for (int i = 0; i < 4; ++i)
                    acc[i][j] = fma2(a2[i], bbv, acc[i][j]);
            }
        }
        __syncthreads();
    }

    #pragma unroll
    for (int i = 0; i < 4; ++i) {
        float2 v[8];
        #pragma unroll
        for (int j = 0; j < 8; ++j) v[j] = unpack2(acc[i][j]);
        #pragma unroll
        for (int p = 0; p < 2; ++p) {
            int m = m0 + ty * 8 + 2 * i + p;
            int t = m & (TT - 1);
            int b = m >> 7;
            float* orow = g_xw + ((size_t)t * BB + b) * HH + n0 + tx * 8;
            float4 o0, o1;
            if (p == 0) {
                o0 = make_float4(v[0].x, v[1].x, v[2].x, v[3].x);
                o1 = make_float4(v[4].x, v[5].x, v[6].x, v[7].x);
            } else {
                o0 = make_float4(v[0].y, v[1].y, v[2].y, v[3].y);
                o1 = make_float4(v[4].y, v[5].y, v[6].y, v[7].y);
            }
            *(float4*)(orow)     = o0;
            *(float4*)(orow + 4) = o1;
        }
    }
}

// ------------------------------------------------------------------
// Step kernel v6: warp-level K-split x8, 8m x 8n per thread.
// CTA tile 32(m) x 64(n), grid 16x8 = 128 CTAs, 256 threads.
// Full K=512 of h tile and Wh slice staged once into smem; each warp
// computes the FULL tile over its K=64 range (sync-free); 8-way smem
// reduction; fused fuzzy-gate epilogue.
// smem: sA [512][36] (h, transposed, 73728B) + sB [512][64] (Wh, 131072B)
//       sRed (ull, stride 33) reuses the sB region after a sync.
// ------------------------------------------------------------------
#define SA_STRIDE 36
#define SA_FLOATS (HH * SA_STRIDE)         // 18432 floats
#define SMEM_STEP_BYTES ((SA_FLOATS + HH * 64) * 4)   // 204800 B

__global__ void __launch_bounds__(256, 1) step_kernel(const float* __restrict__ Wh,
                                                      int t)
{
    extern __shared__ float smem[];
    float* sA = smem;                       // [k][m] stride 36
    float* sB = smem + SA_FLOATS;           // [k][64]
    ull*   sRed = (ull*)sB;                 // reused after GEMM (67584B <= 131072B)

    const int tid = threadIdx.x;
    const int m0  = blockIdx.x * 32;        // grid.x = 16
    const int n0  = blockIdx.y * 64;        // grid.y = 8

    const float* hcur = g_h2[t & 1];
    float*       hnxt = g_h2[(t + 1) & 1];

    const int warp = tid >> 5;
    const int lane = tid & 31;

    // ---- stage A (h tile, 32 x 512) transposed into sA[k][m] ----
    // job f = tid + 256*i : m = (f>>2)&31 is wrong split; use derived:
    //   m = 8*(warp) rows? -> use: m = (tid>>2)&... see mapping below.
    {
        #pragma unroll
        for (int i = 0; i < 16; ++i) {
            int f  = tid + 256 * i;
            int m  = ((f >> 2) & 7) + ((tid >> 5) & 7) * 0; // placeholder avoided
            // mapping: rows grouped by (f>>2)&31 is conflict-prone; use:
            // m = ((f >> 2) & 31) would scatter; instead:
            (void)m; (void)f;
        }
    }
    // Clean staging: m = (lane>>2) + 8*(warp&3) + 16*0 ... use explicit scheme:
    // thread covers: mrow = (lane>>2) + 8*(warp&3); kq = (lane&3) + 4*(warp>>2) + 8*i
    {
        const int mrow = (lane >> 2) + 8 * (warp & 3);     // 0..31
        const int kqb  = (lane & 3) + 4 * (warp >> 2);     // 0..7
        const float* src = hcur + (size_t)(m0 + mrow) * HH;
        #pragma unroll
        for (int i = 0; i < 16; ++i) {
            int kq = kqb + 8 * i;                          // 0..127
            float4 ra = *(const float4*)(src + 4 * kq);
            sA[(4 * kq + 0) * SA_STRIDE + mrow] = ra.x;
            sA[(4 * kq + 1) * SA_STRIDE + mrow] = ra.y;
            sA[(4 * kq + 2) * SA_STRIDE + mrow] = ra.z;
            sA[(4 * kq + 3) * SA_STRIDE + mrow] = ra.w;
        }
    }
    // ---- stage B (Wh slice, 512 x 64) into sB[k][64] ----
    {
        const int n4 = tid & 15;            // float4 col 0..15
        const int kb = tid >> 4;            // 0..15
        #pragma unroll
        for (int i = 0; i < 32; ++i) {
            int k = kb + 16 * i;            // 0..511
            *(float4*)&sB[k * 64 + 4 * n4] =
                *(const float4*)&Wh[(size_t)k * HH + n0 + 4 * n4];
        }
    }
    __syncthreads();

    // ---- GEMM: warp w handles k in [w*64, w*64+64), full 32x64 tile ----
    const int mloc = (lane & 3) * 8;        // 8 m rows
    const int nloc = (lane >> 2) * 8;       // 8 n cols
    const int kbeg = warp * 64;

    ull acc[4][8];
    #pragma unroll
    for (int r = 0; r < 4; ++r)
        #pragma unroll
        for (int j = 0; j < 8; ++j) acc[r][j] = 0ull;

    const float* apb = sA + mloc;
    const float* bpb = sB + nloc;

    #pragma unroll 8
    for (int kk = 0; kk < 64; ++kk) {
        const int k = kbeg + kk;
        const float* ap = apb + k * SA_STRIDE;
        const float* bp = bpb + k * 64;
        ull a0 = *(const ull*)(ap + 0);
        ull a1 = *(const ull*)(ap + 2);
        ull a2 = *(const ull*)(ap + 4);
        ull a3 = *(const ull*)(ap + 6);
        float4 b0 = *(const float4*)(bp);
        float4 b1 = *(const float4*)(bp + 4);
        float bf[8] = {b0.x, b0.y, b0.z, b0.w, b1.x, b1.y, b1.z, b1.w};
        #pragma unroll
        for (int j = 0; j < 8; ++j) {
            ull bb = pack2(bf[j], bf[j]);
            acc[0][j] = fma2(a0, bb, acc[0][j]);
            acc[1][j] = fma2(a1, bb, acc[1][j]);
            acc[2][j] = fma2(a2, bb, acc[2][j]);
            acc[3][j] = fma2(a3, bb, acc[3][j]);
        }
    }

    __syncthreads();    // all warps done reading sB before overwrite

    // ---- write partials: sRed[w*1056 + lane*33 + (r*8+j)] ----
    {
        ull* dst = sRed + warp * 1056 + lane * 33;
        #pragma unroll
        for (int r = 0; r < 4; ++r)
            #pragma unroll
            for (int j = 0; j < 8; ++j)
                dst[r * 8 + j] = acc[r][j];
    }
    __syncthreads();

    // ---- 8-way reduction + fused gate: 4 ulls (2m x 4n) per thread ----
    const int lane_o = tid >> 3;                  // 0..31
    const int aidx0  = (tid & 7) * 4;             // 0..28
    const int i2     = (tid & 7) >> 1;            // acc r
    const int jb     = (tid & 1) * 4;             // n sub-base
    const int mp     = (lane_o & 3) * 8 + 2 * i2; // local m pair base
    const int nb     = (lane_o >> 2) * 8 + jb;    // local n base (mult of 4)

    float2 zs[4];
    #pragma unroll
    for (int s = 0; s < 4; ++s) zs[s] = make_float2(0.f, 0.f);
    #pragma unroll
    for (int w = 0; w < 8; ++w) {
        const ull* src = sRed + w * 1056 + lane_o * 33 + aidx0;
        #pragma unroll
        for (int s = 0; s < 4; ++s) {
            float2 v = unpack2(src[s]);
            zs[s].x += v.x; zs[s].y += v.y;
        }
    }

    // gate params for 2 column-pairs starting at global col n0+nb
    const int colg = n0 + nb;
    float cc[4][3], iv[4][3], qq[4][3], bb2[4];
    #pragma unroll
    for (int jp = 0; jp < 2; ++jp) {
        const float* gp = g_gp + (size_t)((colg >> 1) + jp) * 20;
        float4 p0 = *(const float4*)(gp + 0);
        float4 p1 = *(const float4*)(gp + 4);
        float4 p2 = *(const float4*)(gp + 8);
        float4 p3 = *(const float4*)(gp + 12);
        float4 p4 = *(const float4*)(gp + 16);
        int j0 = jp * 2, j1 = jp * 2 + 1;
        cc[j0][0] = p0.x; cc[j0][1] = p0.y; cc[j0][2] = p0.z; bb2[j0] = p0.w;
        iv[j0][0] = p1.x; iv[j0][1] = p1.y; iv[j0][2] = p1.z;
        qq[j0][0] = p1.w; qq[j0][1] = p2.x; qq[j0][2] = p2.y;
        cc[j1][0] = p2.z; cc[j1][1] = p2.w; cc[j1][2] = p3.x; bb2[j1] = p3.y;
        iv[j1][0] = p3.z; iv[j1][1] = p3.w; iv[j1][2] = p4.x;
        qq[j1][0] = p4.y; qq[j1][1] = p4.z; qq[j1][2] = p4.w;
    }

    const float* xwt = g_xw + (size_t)t * (BB * HH);
    const int r0 = m0 + mp;

    float4 xv0 = *(const float4*)&xwt[(size_t)(r0 + 0) * HH + colg];
    float4 xv1 = *(const float4*)&xwt[(size_t)(r0 + 1) * HH + colg];
    float xa[2][4] = {{xv0.x, xv0.y, xv0.z, xv0.w}, {xv1.x, xv1.y, xv1.z, xv1.w}};

    // hcur from sA (transposed): h[m][col] = sA[col*36 + m]
    float ha[2][4];
    #pragma unroll
    for (int s = 0; s < 4; ++s) {
        float2 h2v = *(const float2*)&sA[(colg + s) * SA_STRIDE + mp];
        ha[0][s] = h2v.x; ha[1][s] = h2v.y;
    }

    float hn[2][4];
    #pragma unroll
    for (int s = 0; s < 4; ++s) {
        #pragma unroll
        for (int p = 0; p < 2; ++p) {
            float x  = xa[p][s];
            float z  = (p ? zs[s].y : zs[s].x) + x + bb2[s];
            float d0 = z - cc[s][0], d1 = z - cc[s][1], d2 = z - cc[s][2];
            float mu0 = __expf(-d0 * d0 * iv[s][0]);
            float mu1 = __expf(-d1 * d1 * iv[s][1]);
            float mu2 = __expf(-d2 * d2 * iv[s][2]);
            float num = mu0 * qq[s][0] + mu1 * qq[s][1] + mu2 * qq[s][2];
            float den = mu0 + mu1 + mu2 + 1e-8f;
            float g   = 1.0f / (1.0f + __expf(-num / den));
            float ex  = __expf(-2.0f * x);
            float ni  = (1.0f - ex) / (1.0f + ex);
            hn[p][s] = (1.0f - g) * ha[p][s] + g * ni;
        }
    }
    *(float4*)&hnxt[(size_t)(r0 + 0) * HH + colg] = make_float4(hn[0][0], hn[0][1], hn[0][2], hn[0][3]);
    *(float4*)&hnxt[(size_t)(r0 + 1) * HH + colg] = make_float4(hn[1][0], hn[1][1], hn[1][2], hn[1][3]);
}

// ------------------------------------------------------------------
// Final: logits[b] = h_final[b] . Wc + bc ; one warp per batch row.
// ------------------------------------------------------------------
__global__ void __launch_bounds__(256) final_kernel(const float* __restrict__ Wc,
                                                    const float* __restrict__ bc,
                                                    float* __restrict__ out)
{
    const int warp = threadIdx.x >> 5;
    const int lane = threadIdx.x & 31;
    const int b = blockIdx.x * 8 + warp;       // 64 blocks x 8 warps = 512
    const float* hrow = g_h2[0] + (size_t)b * HH;
    float s = 0.0f;
    #pragma unroll
    for (int i = 0; i < 4; ++i) {
        float4 h4 = *(const float4*)&hrow[i * 128 + lane * 4];
        float4 w4 = *(const float4*)&Wc[i * 128 + lane * 4];
        s += h4.x * w4.x + h4.y * w4.y + h4.z * w4.z + h4.w * w4.w;
    }
    #pragma unroll
    for (int o = 16; o > 0; o >>= 1) s += __shfl_down_sync(0xffffffffu, s, o);
    if (lane == 0) out[b] = s + bc[0];
}

// ------------------------------------------------------------------
// Launch
// ------------------------------------------------------------------
extern "C" void kernel_launch(void* const* d_in, const int* in_sizes, int n_in,
                              void* d_out, int out_size)
{
    const float* x     = (const float*)d_in[0];
    const float* theta = (const float*)d_in[1];
    const float* Wx    = (const float*)d_in[2];
    const float* Wh    = (const float*)d_in[3];
    const float* bias  = (const float*)d_in[4];
    const float* c     = (const float*)d_in[5];
    const float* sigma = (const float*)d_in[6];
    const float* q     = (const float*)d_in[7];
    const float* Wc    = (const float*)d_in[8];
    const float* bc    = (const float*)d_in[9];
    float* out = (float*)d_out;

    static int configured = 0;
    if (!configured) {
        cudaFuncSetAttribute(step_kernel,
                             cudaFuncAttributeMaxDynamicSharedMemorySize,
                             SMEM_STEP_BYTES);
        configured = 1;
    }

    prep_kernel<<<(BB * HH + 255) / 256, 256>>>(theta, Wx, sigma, c, q, bias, out);
    gemm1_kernel<<<dim3((BB * TT) / 128, HH / 128), 256>>>(x);
    for (int t = 0; t < TT; ++t)
        step_kernel<<<dim3(16, 8), 256, SMEM_STEP_BYTES>>>(Wh, t);
    final_kernel<<<64, 256>>>(Wc, bc, out);
}

// round 9
// speedup vs baseline: 1.8525x; 1.1904x over previous
#include <cuda_runtime.h>
#include <cuda_bf16.h>
#include <math.h>

#define BB   512   // batch
#define TT   128   // time steps
#define FF   256   // features
#define HH   512   // hidden
#define KK   3     // fuzzy rules

typedef unsigned long long ull;
typedef unsigned int uint;

// ------------------------------------------------------------------
// Device scratch
// ------------------------------------------------------------------
__device__ float g_xw[(size_t)TT * BB * HH];          // [T][B][H]
__device__ __nv_bfloat16 g_hh[2][(size_t)BB * HH];    // h hi, ping-pong [B][H]
__device__ __nv_bfloat16 g_hl[2][(size_t)BB * HH];    // h lo
__device__ __nv_bfloat16 g_Whh[HH * HH];              // Wh hi  [k][n]
__device__ __nv_bfloat16 g_Whl[HH * HH];              // Wh lo
__device__ float g_Wxs[FF * HH];                      // diag(sigmoid(theta)) @ Wx
__device__ float g_gp[(HH / 2) * 20];                 // packed gate params / col-pair

// ------------------------------------------------------------------
// Helpers
// ------------------------------------------------------------------
__device__ __forceinline__ ull pack2(float x, float y) {
    ull r; asm("mov.b64 %0, {%1, %2};" : "=l"(r) : "f"(x), "f"(y)); return r;
}
__device__ __forceinline__ float2 unpack2(ull v) {
    float2 r; asm("mov.b64 {%0, %1}, %2;" : "=f"(r.x), "=f"(r.y) : "l"(v)); return r;
}
__device__ __forceinline__ ull fma2(ull a, ull b, ull c) {
    ull d; asm("fma.rn.f32x2 %0, %1, %2, %3;" : "=l"(d) : "l"(a), "l"(b), "l"(c)); return d;
}
__device__ __forceinline__ uint smem_u32(const void* p) {
    return (uint)__cvta_generic_to_shared(p);
}
__device__ __forceinline__ void ldmx4(uint* r, uint addr) {
    asm volatile("ldmatrix.sync.aligned.m8n8.x4.shared.b16 {%0,%1,%2,%3}, [%4];"
                 : "=r"(r[0]), "=r"(r[1]), "=r"(r[2]), "=r"(r[3]) : "r"(addr));
}
__device__ __forceinline__ void ldmx4t(uint* r, uint addr) {
    asm volatile("ldmatrix.sync.aligned.m8n8.x4.trans.shared.b16 {%0,%1,%2,%3}, [%4];"
                 : "=r"(r[0]), "=r"(r[1]), "=r"(r[2]), "=r"(r[3]) : "r"(addr));
}
__device__ __forceinline__ void mma16816(float* d, const uint* a, uint b0, uint b1) {
    asm volatile("mma.sync.aligned.m16n8k16.row.col.f32.bf16.bf16.f32 "
                 "{%0,%1,%2,%3}, {%4,%5,%6,%7}, {%8,%9}, {%0,%1,%2,%3};"
                 : "+f"(d[0]), "+f"(d[1]), "+f"(d[2]), "+f"(d[3])
                 : "r"(a[0]), "r"(a[1]), "r"(a[2]), "r"(a[3]), "r"(b0), "r"(b1));
}

// ------------------------------------------------------------------
// Prep: zero h0 (hi/lo), split Wh into bf16 hi/lo, fold selector into Wx,
// emit weights output, pack gate params.
// ------------------------------------------------------------------
__global__ void prep_kernel(const float* __restrict__ theta,
                            const float* __restrict__ Wx,
                            const float* __restrict__ Wh,
                            const float* __restrict__ sigma,
                            const float* __restrict__ cC,
                            const float* __restrict__ qQ,
                            const float* __restrict__ bias,
                            float* __restrict__ out)
{
    int idx = blockIdx.x * blockDim.x + threadIdx.x;   // 262144 threads
    if (idx < BB * HH) {
        g_hh[0][idx] = __float2bfloat16_rn(0.0f);
        g_hl[0][idx] = __float2bfloat16_rn(0.0f);
    }
    if (idx < HH * HH) {
        float w = Wh[idx];
        __nv_bfloat16 hi = __float2bfloat16_rn(w);
        float lo = w - __bfloat162float(hi);
        g_Whh[idx] = hi;
        g_Whl[idx] = __float2bfloat16_rn(lo);
    }
    if (idx < FF * HH) {
        int f = idx >> 9;
        float w = 1.0f / (1.0f + expf(-theta[f]));
        g_Wxs[idx] = w * Wx[idx];
    }
    if (idx < FF) out[BB + idx] = 1.0f / (1.0f + expf(-theta[idx]));
    if (idx < HH / 2) {
        float* gp = g_gp + idx * 20;
        #pragma unroll
        for (int j = 0; j < 2; ++j) {
            int col = idx * 2 + j;
            float* o = gp + j * 10;
            #pragma unroll
            for (int s = 0; s < 3; ++s) {
                float sg = sigma[col * 3 + s];
                o[0 + s] = cC[col * 3 + s];
                o[4 + s] = 1.0f / (2.0f * sg * sg + 1e-8f);
                o[7 + s] = qQ[col * 3 + s];
            }
            o[3] = bias[col];
        }
    }
}

// ------------------------------------------------------------------
// GEMM1 (proven, FFMA2): g_xw[t][b][h] = sum_f x[b][t][f] * Wxs[f][h]
// ------------------------------------------------------------------
__global__ void __launch_bounds__(256) gemm1_kernel(const float* __restrict__ x)
{
    __shared__ float sA[16][130];
    __shared__ float sB[16][128];

    const int tid = threadIdx.x;
    const int m0  = blockIdx.x * 128;
    const int n0  = blockIdx.y * 128;

    const int ar = tid >> 1;
    const int ak = (tid & 1) * 8;
    const int bk = tid >> 4;
    const int bc = (tid & 15) * 8;

    const float* Ag = x     + (size_t)(m0 + ar) * FF + ak;
    const float* Bg = g_Wxs + (size_t)bk * HH + n0 + bc;

    float4 ra0 = *(const float4*)(Ag);
    float4 ra1 = *(const float4*)(Ag + 4);
    float4 rb0 = *(const float4*)(Bg);
    float4 rb1 = *(const float4*)(Bg + 4);

    ull acc[4][8];
    #pragma unroll
    for (int i = 0; i < 4; ++i)
        #pragma unroll
        for (int j = 0; j < 8; ++j) acc[i][j] = 0ull;

    const int ty = tid >> 4;
    const int tx = tid & 15;

    #pragma unroll 1
    for (int kt = 0; kt < FF / 16; ++kt) {
        sA[ak + 0][ar] = ra0.x; sA[ak + 1][ar] = ra0.y;
        sA[ak + 2][ar] = ra0.z; sA[ak + 3][ar] = ra0.w;
        sA[ak + 4][ar] = ra1.x; sA[ak + 5][ar] = ra1.y;
        sA[ak + 6][ar] = ra1.z; sA[ak + 7][ar] = ra1.w;
        *(float4*)&sB[bk][bc]     = rb0;
        *(float4*)&sB[bk][bc + 4] = rb1;
        __syncthreads();

        if (kt < FF / 16 - 1) {
            const float* Ag2 = Ag + (kt + 1) * 16;
            const float* Bg2 = Bg + (size_t)(kt + 1) * 16 * HH;
            ra0 = *(const float4*)(Ag2);
            ra1 = *(const float4*)(Ag2 + 4);
            rb0 = *(const float4*)(Bg2);
            rb1 = *(const float4*)(Bg2 + 4);
        }

        #pragma unroll
        for (int kk = 0; kk < 16; ++kk) {
            ull a2[4];
            #pragma unroll
            for (int i = 0; i < 4; ++i)
                a2[i] = *(const ull*)&sA[kk][ty * 8 + 2 * i];
            float bf[8];
            *(float4*)&bf[0] = *(const float4*)&sB[kk][tx * 8];
            *(float4*)&bf[4] = *(const float4*)&sB[kk][tx * 8 + 4];
            #pragma unroll
            for (int j = 0; j < 8; ++j) {
                ull bbv = pack2(bf[j], bf[j]);
                #pragma unroll
                for (int i = 0; i < 4; ++i)
                    acc[i][j] = fma2(a2[i], bbv, acc[i][j]);
            }
        }
        __syncthreads();
    }

    #pragma unroll
    for (int i = 0; i < 4; ++i) {
        float2 v[8];
        #pragma unroll
        for (int j = 0; j < 8; ++j) v[j] = unpack2(acc[i][j]);
        #pragma unroll
        for (int p = 0; p < 2; ++p) {
            int m = m0 + ty * 8 + 2 * i + p;
            int t = m & (TT - 1);
            int b = m >> 7;
            float* orow = g_xw + ((size_t)t * BB + b) * HH + n0 + tx * 8;
            float4 o0, o1;
            if (p == 0) {
                o0 = make_float4(v[0].x, v[1].x, v[2].x, v[3].x);
                o1 = make_float4(v[4].x, v[5].x, v[6].x, v[7].x);
            } else {
                o0 = make_float4(v[0].y, v[1].y, v[2].y, v[3].y);
                o1 = make_float4(v[4].y, v[5].y, v[6].y, v[7].y);
            }
            *(float4*)(orow)     = o0;
            *(float4*)(orow + 4) = o1;
        }
    }
}

// ------------------------------------------------------------------
// Step kernel v7: HMMA bf16 hi/lo split-precision.
// CTA tile 32(m) x 64(n), K=512, grid 16x8 = 128 CTAs, 256 threads.
// z = h_hi@W_hi + h_hi@W_lo + h_lo@W_hi  (fp32 accum, lo*lo dropped)
// 8 warps = 2(m16) x 4(n16) positions, each warp full K, no reduction.
// smem: sAh/sAl [32][520] bf16, sBh/sBl [512][72] bf16 = 209 KB.
// ------------------------------------------------------------------
#define SA_PITCH 520            // bf16 per A row (pad 8)
#define SB_PITCH 72             // bf16 per B row (pad 8)
#define SMEM_AH  0
#define SMEM_AL  (32 * SA_PITCH * 2)                    // 33280
#define SMEM_BH  (2 * 32 * SA_PITCH * 2)                // 66560
#define SMEM_BL  (SMEM_BH + HH * SB_PITCH * 2)          // 140288
#define SMEM_STEP_BYTES (SMEM_BL + HH * SB_PITCH * 2)   // 214016

__global__ void __launch_bounds__(256, 1) step_kernel(int t)
{
    extern __shared__ char smem[];
    __nv_bfloat16* sAh = (__nv_bfloat16*)(smem + SMEM_AH);
    __nv_bfloat16* sAl = (__nv_bfloat16*)(smem + SMEM_AL);
    __nv_bfloat16* sBh = (__nv_bfloat16*)(smem + SMEM_BH);
    __nv_bfloat16* sBl = (__nv_bfloat16*)(smem + SMEM_BL);

    const int tid = threadIdx.x;
    const int m0  = blockIdx.x * 32;    // grid.x = 16
    const int n0  = blockIdx.y * 64;    // grid.y = 8

    const __nv_bfloat16* hh = g_hh[t & 1];
    const __nv_bfloat16* hl = g_hl[t & 1];

    // ---- stage A (h hi/lo): 32 rows x 512 bf16, straight row-major copy ----
    {
        const uint4* srcH = (const uint4*)(hh + (size_t)m0 * HH);
        const uint4* srcL = (const uint4*)(hl + (size_t)m0 * HH);
        #pragma unroll
        for (int j = 0; j < 8; ++j) {
            int flat = tid + 256 * j;          // < 2048
            int row  = flat >> 6;              // 0..31
            int c8   = flat & 63;              // uint4 within row
            uint4 vh = srcH[row * 64 + c8];
            uint4 vl = srcL[row * 64 + c8];
            *(uint4*)(sAh + row * SA_PITCH + c8 * 8) = vh;
            *(uint4*)(sAl + row * SA_PITCH + c8 * 8) = vl;
        }
    }
    // ---- stage B (Wh hi/lo slice): 512 rows x 64 bf16 ----
    {
        #pragma unroll
        for (int j = 0; j < 16; ++j) {
            int flat = tid + 256 * j;          // < 4096
            int row  = flat >> 3;              // 0..511
            int c8   = flat & 7;
            uint4 vh = *(const uint4*)(g_Whh + (size_t)row * HH + n0 + c8 * 8);
            uint4 vl = *(const uint4*)(g_Whl + (size_t)row * HH + n0 + c8 * 8);
            *(uint4*)(sBh + row * SB_PITCH + c8 * 8) = vh;
            *(uint4*)(sBl + row * SB_PITCH + c8 * 8) = vl;
        }
    }
    __syncthreads();

    // ---- HMMA mainloop ----
    const int warp = tid >> 5;
    const int lane = tid & 31;
    const int mw   = warp & 1;          // m16 tile
    const int nw   = warp >> 1;         // n16 tile (0..3)

    // ldmatrix lane addresses
    const int aRow = mw * 16 + (lane & 15);
    const int aCol = (lane >> 4) * 8;
    uint aAddrH = smem_u32(sAh + aRow * SA_PITCH + aCol);
    uint aAddrL = aAddrH + (SMEM_AL - SMEM_AH);

    const int bRow = lane & 15;
    const int bCol = nw * 16 + (lane >> 4) * 8;
    uint bAddrH = smem_u32(sBh + bRow * SB_PITCH + bCol);
    uint bAddrL = bAddrH + (SMEM_BL - SMEM_BH);

    float acc0[4] = {0.f, 0.f, 0.f, 0.f};   // cols nw*16 + 0..7
    float acc1[4] = {0.f, 0.f, 0.f, 0.f};   // cols nw*16 + 8..15

    #pragma unroll 4
    for (int ks = 0; ks < 32; ++ks) {
        uint ah[4], al[4], bh[4], bl[4];
        ldmx4 (ah, aAddrH + ks * 32);                 // +16 bf16 per slab
        ldmx4 (al, aAddrL + ks * 32);
        ldmx4t(bh, bAddrH + ks * (16 * SB_PITCH * 2));
        ldmx4t(bl, bAddrL + ks * (16 * SB_PITCH * 2));
        mma16816(acc0, ah, bh[0], bh[1]);
        mma16816(acc0, ah, bl[0], bl[1]);
        mma16816(acc0, al, bh[0], bh[1]);
        mma16816(acc1, ah, bh[2], bh[3]);
        mma16816(acc1, ah, bl[2], bl[3]);
        mma16816(acc1, al, bh[2], bh[3]);
    }

    // ---- fused gate epilogue ----
    const float* xwt = g_xw + (size_t)t * (BB * HH);
    __nv_bfloat16* hhn = g_hh[(t + 1) & 1];
    __nv_bfloat16* hln = g_hl[(t + 1) & 1];

    const int rl0 = mw * 16 + (lane >> 2);    // local row (second = +8)
    const int c0  = (lane & 3) * 2;           // even col offset within n8

    float* accs[2] = {acc0, acc1};
    #pragma unroll
    for (int half = 0; half < 2; ++half) {
        const float* d = accs[half];
        const int colg = n0 + nw * 16 + half * 8 + c0;     // global col, even

        const float* gp = g_gp + (size_t)(colg >> 1) * 20;
        float4 p0 = *(const float4*)(gp + 0);
        float4 p1 = *(const float4*)(gp + 4);
        float4 p2 = *(const float4*)(gp + 8);
        float4 p3 = *(const float4*)(gp + 12);
        float4 p4 = *(const float4*)(gp + 16);
        float cc[2][3]  = {{p0.x, p0.y, p0.z}, {p2.z, p2.w, p3.x}};
        float bb2[2]    = {p0.w, p3.y};
        float iv[2][3]  = {{p1.x, p1.y, p1.z}, {p3.z, p3.w, p4.x}};
        float qq[2][3]  = {{p1.w, p2.x, p2.y}, {p4.y, p4.z, p4.w}};

        #pragma unroll
        for (int p = 0; p < 2; ++p) {
            const int rl = rl0 + p * 8;               // local row
            const int rg = m0 + rl;                   // global row
            float2 xv = *(const float2*)&xwt[(size_t)rg * HH + colg];
            __nv_bfloat162 hhi = *(const __nv_bfloat162*)(sAh + rl * SA_PITCH + colg);
            __nv_bfloat162 hlo = *(const __nv_bfloat162*)(sAl + rl * SA_PITCH + colg);
            float hin[2] = {__low2float(hhi) + __low2float(hlo),
                            __high2float(hhi) + __high2float(hlo)};
            float zz[2] = {d[2 * p + 0] + xv.x, d[2 * p + 1] + xv.y};
            float xa[2] = {xv.x, xv.y};
            float hn[2];
            #pragma unroll
            for (int j = 0; j < 2; ++j) {
                float z  = zz[j] + bb2[j];
                float d0 = z - cc[j][0], d1 = z - cc[j][1], d2 = z - cc[j][2];
                float mu0 = __expf(-d0 * d0 * iv[j][0]);
                float mu1 = __expf(-d1 * d1 * iv[j][1]);
                float mu2 = __expf(-d2 * d2 * iv[j][2]);
                float num = mu0 * qq[j][0] + mu1 * qq[j][1] + mu2 * qq[j][2];
                float den = mu0 + mu1 + mu2 + 1e-8f;
                float g   = 1.0f / (1.0f + __expf(-num / den));
                float ex  = __expf(-2.0f * xa[j]);
                float ni  = (1.0f - ex) / (1.0f + ex);
                hn[j] = (1.0f - g) * hin[j] + g * ni;
            }
            // split hn into bf16 hi/lo and store
            __nv_bfloat16 h0i = __float2bfloat16_rn(hn[0]);
            __nv_bfloat16 h1i = __float2bfloat16_rn(hn[1]);
            float l0 = hn[0] - __bfloat162float(h0i);
            float l1 = hn[1] - __bfloat162float(h1i);
            __nv_bfloat162 hiv; hiv.x = h0i; hiv.y = h1i;
            __nv_bfloat162 lov; lov.x = __float2bfloat16_rn(l0);
            lov.y = __float2bfloat16_rn(l1);
            *(__nv_bfloat162*)&hhn[(size_t)rg * HH + colg] = hiv;
            *(__nv_bfloat162*)&hln[(size_t)rg * HH + colg] = lov;
        }
    }
}

// ------------------------------------------------------------------
// Final: logits[b] = h_final[b] . Wc + bc ; one warp per batch row.
// h_final = g_hh[0] + g_hl[0]  (TT even).
// ------------------------------------------------------------------
__global__ void __launch_bounds__(256) final_kernel(const float* __restrict__ Wc,
                                                    const float* __restrict__ bc,
                                                    float* __restrict__ out)
{
    const int warp = threadIdx.x >> 5;
    const int lane = threadIdx.x & 31;
    const int b = blockIdx.x * 8 + warp;       // 64 blocks x 8 warps = 512
    const __nv_bfloat16* hhr = g_hh[0] + (size_t)b * HH;
    const __nv_bfloat16* hlr = g_hl[0] + (size_t)b * HH;
    float s = 0.0f;
    #pragma unroll
    for (int i = 0; i < 4; ++i) {
        int h = i * 128 + lane * 4;
        __nv_bfloat162 a0 = *(const __nv_bfloat162*)(hhr + h);
        __nv_bfloat162 a1 = *(const __nv_bfloat162*)(hhr + h + 2);
        __nv_bfloat162 l0 = *(const __nv_bfloat162*)(hlr + h);
        __nv_bfloat162 l1 = *(const __nv_bfloat162*)(hlr + h + 2);
        float4 w4 = *(const float4*)&Wc[h];
        s += (__low2float(a0)  + __low2float(l0))  * w4.x;
        s += (__high2float(a0) + __high2float(l0)) * w4.y;
        s += (__low2float(a1)  + __low2float(l1))  * w4.z;
        s += (__high2float(a1) + __high2float(l1)) * w4.w;
    }
    #pragma unroll
    for (int o = 16; o > 0; o >>= 1) s += __shfl_down_sync(0xffffffffu, s, o);
    if (lane == 0) out[b] = s + bc[0];
}

// ------------------------------------------------------------------
// Launch
// ------------------------------------------------------------------
extern "C" void kernel_launch(void* const* d_in, const int* in_sizes, int n_in,
                              void* d_out, int out_size)
{
    const float* x     = (const float*)d_in[0];
    const float* theta = (const float*)d_in[1];
    const float* Wx    = (const float*)d_in[2];
    const float* Wh    = (const float*)d_in[3];
    const float* bias  = (const float*)d_in[4];
    const float* c     = (const float*)d_in[5];
    const float* sigma = (const float*)d_in[6];
    const float* q     = (const float*)d_in[7];
    const float* Wc    = (const float*)d_in[8];
    const float* bc    = (const float*)d_in[9];
    float* out = (float*)d_out;

    static int configured = 0;
    if (!configured) {
        cudaFuncSetAttribute(step_kernel,
                             cudaFuncAttributeMaxDynamicSharedMemorySize,
                             SMEM_STEP_BYTES);
        configured = 1;
    }

    prep_kernel<<<(BB * HH + 255) / 256, 256>>>(theta, Wx, Wh, sigma, c, q, bias, out);
    gemm1_kernel<<<dim3((BB * TT) / 128, HH / 128), 256>>>(x);
    for (int t = 0; t < TT; ++t)
        step_kernel<<<dim3(16, 8), 256, SMEM_STEP_BYTES>>>(t);
    final_kernel<<<64, 256>>>(Wc, bc, out);
}

// round 10
// speedup vs baseline: 2.0135x; 1.0869x over previous
#include <cuda_runtime.h>
#include <cuda_bf16.h>
#include <math.h>

#define BB   512   // batch
#define TT   128   // time steps
#define FF   256   // features
#define HH   512   // hidden
#define KK   3     // fuzzy rules

typedef unsigned long long ull;
typedef unsigned int uint;

// ------------------------------------------------------------------
// Device scratch
// ------------------------------------------------------------------
__device__ float g_xw[(size_t)TT * BB * HH];          // [T][B][H]
__device__ __nv_bfloat16 g_hh[2][(size_t)BB * HH];    // h hi, ping-pong [B][H]
__device__ __nv_bfloat16 g_hl[2][(size_t)BB * HH];    // h lo
__device__ __nv_bfloat16 g_Whh[HH * HH];              // Wh hi  [k][n]
__device__ __nv_bfloat16 g_Whl[HH * HH];              // Wh lo
__device__ __nv_bfloat16 g_Wxh[FF * HH];              // (sigmoid(theta)*Wx) hi
__device__ __nv_bfloat16 g_Wxl[FF * HH];              // (sigmoid(theta)*Wx) lo
__device__ __nv_bfloat16 g_xh[(size_t)BB * TT * FF];  // x hi  [b*T+t][f]
__device__ __nv_bfloat16 g_xl[(size_t)BB * TT * FF];  // x lo
__device__ float g_gp[(HH / 2) * 20];                 // packed gate params / col-pair

// ------------------------------------------------------------------
// Helpers
// ------------------------------------------------------------------
__device__ __forceinline__ uint smem_u32(const void* p) {
    return (uint)__cvta_generic_to_shared(p);
}
__device__ __forceinline__ void ldmx4(uint* r, uint addr) {
    asm volatile("ldmatrix.sync.aligned.m8n8.x4.shared.b16 {%0,%1,%2,%3}, [%4];"
                 : "=r"(r[0]), "=r"(r[1]), "=r"(r[2]), "=r"(r[3]) : "r"(addr));
}
__device__ __forceinline__ void ldmx4t(uint* r, uint addr) {
    asm volatile("ldmatrix.sync.aligned.m8n8.x4.trans.shared.b16 {%0,%1,%2,%3}, [%4];"
                 : "=r"(r[0]), "=r"(r[1]), "=r"(r[2]), "=r"(r[3]) : "r"(addr));
}
__device__ __forceinline__ void mma16816(float* d, const uint* a, uint b0, uint b1) {
    asm volatile("mma.sync.aligned.m16n8k16.row.col.f32.bf16.bf16.f32 "
                 "{%0,%1,%2,%3}, {%4,%5,%6,%7}, {%8,%9}, {%0,%1,%2,%3};"
                 : "+f"(d[0]), "+f"(d[1]), "+f"(d[2]), "+f"(d[3])
                 : "r"(a[0]), "r"(a[1]), "r"(a[2]), "r"(a[3]), "r"(b0), "r"(b1));
}

// ------------------------------------------------------------------
// Prep: zero h0, split Wh and Wxs into bf16 hi/lo, emit weights, gate params.
// ------------------------------------------------------------------
__global__ void prep_kernel(const float* __restrict__ theta,
                            const float* __restrict__ Wx,
                            const float* __restrict__ Wh,
                            const float* __restrict__ sigma,
                            const float* __restrict__ cC,
                            const float* __restrict__ qQ,
                            const float* __restrict__ bias,
                            float* __restrict__ out)
{
    int idx = blockIdx.x * blockDim.x + threadIdx.x;   // 262144 threads
    if (idx < BB * HH) {
        g_hh[0][idx] = __float2bfloat16_rn(0.0f);
        g_hl[0][idx] = __float2bfloat16_rn(0.0f);
    }
    if (idx < HH * HH) {
        float w = Wh[idx];
        __nv_bfloat16 hi = __float2bfloat16_rn(w);
        g_Whh[idx] = hi;
        g_Whl[idx] = __float2bfloat16_rn(w - __bfloat162float(hi));
    }
    if (idx < FF * HH) {
        int f = idx >> 9;
        float w = (1.0f / (1.0f + expf(-theta[f]))) * Wx[idx];
        __nv_bfloat16 hi = __float2bfloat16_rn(w);
        g_Wxh[idx] = hi;
        g_Wxl[idx] = __float2bfloat16_rn(w - __bfloat162float(hi));
    }
    if (idx < FF) out[BB + idx] = 1.0f / (1.0f + expf(-theta[idx]));
    if (idx < HH / 2) {
        float* gp = g_gp + idx * 20;
        #pragma unroll
        for (int j = 0; j < 2; ++j) {
            int col = idx * 2 + j;
            float* o = gp + j * 10;
            #pragma unroll
            for (int s = 0; s < 3; ++s) {
                float sg = sigma[col * 3 + s];
                o[0 + s] = cC[col * 3 + s];
                o[4 + s] = 1.0f / (2.0f * sg * sg + 1e-8f);
                o[7 + s] = qQ[col * 3 + s];
            }
            o[3] = bias[col];
        }
    }
}

// ------------------------------------------------------------------
// x -> bf16 hi/lo split. 4 floats per thread, 16384 blocks x 256.
// ------------------------------------------------------------------
__global__ void __launch_bounds__(256) xcvt_kernel(const float* __restrict__ x)
{
    size_t i = ((size_t)blockIdx.x * 256 + threadIdx.x) * 4;
    float4 v = *(const float4*)(x + i);
    __nv_bfloat16 h0 = __float2bfloat16_rn(v.x);
    __nv_bfloat16 h1 = __float2bfloat16_rn(v.y);
    __nv_bfloat16 h2 = __float2bfloat16_rn(v.z);
    __nv_bfloat16 h3 = __float2bfloat16_rn(v.w);
    __nv_bfloat162 hv0; hv0.x = h0; hv0.y = h1;
    __nv_bfloat162 hv1; hv1.x = h2; hv1.y = h3;
    __nv_bfloat162 lv0;
    lv0.x = __float2bfloat16_rn(v.x - __bfloat162float(h0));
    lv0.y = __float2bfloat16_rn(v.y - __bfloat162float(h1));
    __nv_bfloat162 lv1;
    lv1.x = __float2bfloat16_rn(v.z - __bfloat162float(h2));
    lv1.y = __float2bfloat16_rn(v.w - __bfloat162float(h3));
    *(__nv_bfloat162*)(g_xh + i)     = hv0;
    *(__nv_bfloat162*)(g_xh + i + 2) = hv1;
    *(__nv_bfloat162*)(g_xl + i)     = lv0;
    *(__nv_bfloat162*)(g_xl + i + 2) = lv1;
}

// ------------------------------------------------------------------
// GEMM1 (HMMA hi/lo): g_xw[t][b][h] = sum_f x[m][f] * Wxs[f][h], m=b*T+t.
// CTA tile 64m x 128n, K=256 fully staged. Grid (1024, 4), 256 threads.
// 8 warps = 2(m32) x 4(n32); per warp 2 m16 x 4 n8 accs, 3-term hi/lo.
// ------------------------------------------------------------------
#define SA1_PITCH 264
#define SB1_PITCH 136
#define SM1_AH 0
#define SM1_AL (64 * SA1_PITCH * 2)                    // 33792
#define SM1_BH (2 * 64 * SA1_PITCH * 2)                // 67584
#define SM1_BL (SM1_BH + FF * SB1_PITCH * 2)           // 137216
#define SMEM_G1_BYTES (SM1_BL + FF * SB1_PITCH * 2)    // 206848

__global__ void __launch_bounds__(256, 1) gemm1_hmma()
{
    extern __shared__ char smem[];
    __nv_bfloat16* sAh = (__nv_bfloat16*)(smem + SM1_AH);
    __nv_bfloat16* sAl = (__nv_bfloat16*)(smem + SM1_AL);
    __nv_bfloat16* sBh = (__nv_bfloat16*)(smem + SM1_BH);
    __nv_bfloat16* sBl = (__nv_bfloat16*)(smem + SM1_BL);

    const int tid = threadIdx.x;
    const int m0  = blockIdx.x * 64;     // grid.x = 1024
    const int n0  = blockIdx.y * 128;    // grid.y = 4

    // ---- stage A (x hi/lo): 64 rows x 256 bf16 ----
    {
        #pragma unroll
        for (int j = 0; j < 8; ++j) {
            int flat = tid + 256 * j;          // < 2048
            int row  = flat >> 5;              // 0..63
            int c8   = flat & 31;              // uint4 within row (32 per row)
            const size_t src = (size_t)(m0 + row) * FF + c8 * 8;
            *(uint4*)(sAh + row * SA1_PITCH + c8 * 8) = *(const uint4*)(g_xh + src);
            *(uint4*)(sAl + row * SA1_PITCH + c8 * 8) = *(const uint4*)(g_xl + src);
        }
    }
    // ---- stage B (Wxs hi/lo): 256 rows x 128 bf16 ----
    {
        #pragma unroll
        for (int j = 0; j < 16; ++j) {
            int flat = tid + 256 * j;          // < 4096
            int row  = flat >> 4;              // 0..255
            int c8   = flat & 15;              // 16 uint4 per row
            const size_t src = (size_t)row * HH + n0 + c8 * 8;
            *(uint4*)(sBh + row * SB1_PITCH + c8 * 8) = *(const uint4*)(g_Wxh + src);
            *(uint4*)(sBl + row * SB1_PITCH + c8 * 8) = *(const uint4*)(g_Wxl + src);
        }
    }
    __syncthreads();

    const int warp = tid >> 5;
    const int lane = tid & 31;
    const int mw   = warp & 1;           // m32 tile
    const int nw   = warp >> 1;          // n32 tile (0..3)

    // ldmatrix base addresses
    uint aAddrH[2], aAddrL[2];
    #pragma unroll
    for (int a = 0; a < 2; ++a) {
        int aRow = mw * 32 + a * 16 + (lane & 15);
        int aCol = (lane >> 4) * 8;
        aAddrH[a] = smem_u32(sAh + aRow * SA1_PITCH + aCol);
        aAddrL[a] = aAddrH[a] + (SM1_AL - SM1_AH);
    }
    uint bAddrH[2], bAddrL[2];
    #pragma unroll
    for (int bsub = 0; bsub < 2; ++bsub) {
        int bRow = lane & 15;
        int bCol = nw * 32 + bsub * 16 + (lane >> 4) * 8;
        bAddrH[bsub] = smem_u32(sBh + bRow * SB1_PITCH + bCol);
        bAddrL[bsub] = bAddrH[bsub] + (SM1_BL - SM1_BH);
    }

    float acc[2][4][4];
    #pragma unroll
    for (int a = 0; a < 2; ++a)
        #pragma unroll
        for (int j = 0; j < 4; ++j)
            #pragma unroll
            for (int r = 0; r < 4; ++r) acc[a][j][r] = 0.f;

    #pragma unroll 2
    for (int ks = 0; ks < 16; ++ks) {
        uint ah[2][4], al[2][4], bh[2][4], bl[2][4];
        #pragma unroll
        for (int a = 0; a < 2; ++a) {
            ldmx4(ah[a], aAddrH[a] + ks * 32);
            ldmx4(al[a], aAddrL[a] + ks * 32);
        }
        #pragma unroll
        for (int bsub = 0; bsub < 2; ++bsub) {
            ldmx4t(bh[bsub], bAddrH[bsub] + ks * (16 * SB1_PITCH * 2));
            ldmx4t(bl[bsub], bAddrL[bsub] + ks * (16 * SB1_PITCH * 2));
        }
        #pragma unroll
        for (int a = 0; a < 2; ++a) {
            #pragma unroll
            for (int bsub = 0; bsub < 2; ++bsub) {
                float* d0 = acc[a][bsub * 2 + 0];
                float* d1 = acc[a][bsub * 2 + 1];
                mma16816(d0, ah[a], bh[bsub][0], bh[bsub][1]);
                mma16816(d0, ah[a], bl[bsub][0], bl[bsub][1]);
                mma16816(d0, al[a], bh[bsub][0], bh[bsub][1]);
                mma16816(d1, ah[a], bh[bsub][2], bh[bsub][3]);
                mma16816(d1, ah[a], bl[bsub][2], bl[bsub][3]);
                mma16816(d1, al[a], bh[bsub][2], bh[bsub][3]);
            }
        }
    }

    // ---- epilogue: write fp32 xw in [t][b][h] layout ----
    #pragma unroll
    for (int a = 0; a < 2; ++a) {
        #pragma unroll
        for (int j = 0; j < 4; ++j) {
            const int col = n0 + nw * 32 + j * 8 + (lane & 3) * 2;
            #pragma unroll
            for (int p = 0; p < 2; ++p) {
                int rl = mw * 32 + a * 16 + (lane >> 2) + p * 8;
                int m  = m0 + rl;
                int t  = m & (TT - 1);
                int b  = m >> 7;
                float2 v = make_float2(acc[a][j][2 * p], acc[a][j][2 * p + 1]);
                *(float2*)&g_xw[((size_t)t * BB + b) * HH + col] = v;
            }
        }
    }
}

// ------------------------------------------------------------------
// Step kernel v7 (unchanged, proven): HMMA bf16 hi/lo split-precision.
// ------------------------------------------------------------------
#define SA_PITCH 520
#define SB_PITCH 72
#define SMEM_AH  0
#define SMEM_AL  (32 * SA_PITCH * 2)
#define SMEM_BH  (2 * 32 * SA_PITCH * 2)
#define SMEM_BL  (SMEM_BH + HH * SB_PITCH * 2)
#define SMEM_STEP_BYTES (SMEM_BL + HH * SB_PITCH * 2)

__global__ void __launch_bounds__(256, 1) step_kernel(int t)
{
    extern __shared__ char smem[];
    __nv_bfloat16* sAh = (__nv_bfloat16*)(smem + SMEM_AH);
    __nv_bfloat16* sAl = (__nv_bfloat16*)(smem + SMEM_AL);
    __nv_bfloat16* sBh = (__nv_bfloat16*)(smem + SMEM_BH);
    __nv_bfloat16* sBl = (__nv_bfloat16*)(smem + SMEM_BL);

    const int tid = threadIdx.x;
    const int m0  = blockIdx.x * 32;
    const int n0  = blockIdx.y * 64;

    const __nv_bfloat16* hh = g_hh[t & 1];
    const __nv_bfloat16* hl = g_hl[t & 1];

    {
        const uint4* srcH = (const uint4*)(hh + (size_t)m0 * HH);
        const uint4* srcL = (const uint4*)(hl + (size_t)m0 * HH);
        #pragma unroll
        for (int j = 0; j < 8; ++j) {
            int flat = tid + 256 * j;
            int row  = flat >> 6;
            int c8   = flat & 63;
            *(uint4*)(sAh + row * SA_PITCH + c8 * 8) = srcH[row * 64 + c8];
            *(uint4*)(sAl + row * SA_PITCH + c8 * 8) = srcL[row * 64 + c8];
        }
    }
    {
        #pragma unroll
        for (int j = 0; j < 16; ++j) {
            int flat = tid + 256 * j;
            int row  = flat >> 3;
            int c8   = flat & 7;
            *(uint4*)(sBh + row * SB_PITCH + c8 * 8) =
                *(const uint4*)(g_Whh + (size_t)row * HH + n0 + c8 * 8);
            *(uint4*)(sBl + row * SB_PITCH + c8 * 8) =
                *(const uint4*)(g_Whl + (size_t)row * HH + n0 + c8 * 8);
        }
    }
    __syncthreads();

    const int warp = tid >> 5;
    const int lane = tid & 31;
    const int mw   = warp & 1;
    const int nw   = warp >> 1;

    const int aRow = mw * 16 + (lane & 15);
    const int aCol = (lane >> 4) * 8;
    uint aAddrH = smem_u32(sAh + aRow * SA_PITCH + aCol);
    uint aAddrL = aAddrH + (SMEM_AL - SMEM_AH);

    const int bRow = lane & 15;
    const int bCol = nw * 16 + (lane >> 4) * 8;
    uint bAddrH = smem_u32(sBh + bRow * SB_PITCH + bCol);
    uint bAddrL = bAddrH + (SMEM_BL - SMEM_BH);

    float acc0[4] = {0.f, 0.f, 0.f, 0.f};
    float acc1[4] = {0.f, 0.f, 0.f, 0.f};

    #pragma unroll 4
    for (int ks = 0; ks < 32; ++ks) {
        uint ah[4], al[4], bh[4], bl[4];
        ldmx4 (ah, aAddrH + ks * 32);
        ldmx4 (al, aAddrL + ks * 32);
        ldmx4t(bh, bAddrH + ks * (16 * SB_PITCH * 2));
        ldmx4t(bl, bAddrL + ks * (16 * SB_PITCH * 2));
        mma16816(acc0, ah, bh[0], bh[1]);
        mma16816(acc0, ah, bl[0], bl[1]);
        mma16816(acc0, al, bh[0], bh[1]);
        mma16816(acc1, ah, bh[2], bh[3]);
        mma16816(acc1, ah, bl[2], bl[3]);
        mma16816(acc1, al, bh[2], bh[3]);
    }

    const float* xwt = g_xw + (size_t)t * (BB * HH);
    __nv_bfloat16* hhn = g_hh[(t + 1) & 1];
    __nv_bfloat16* hln = g_hl[(t + 1) & 1];

    const int rl0 = mw * 16 + (lane >> 2);
    const int c0  = (lane & 3) * 2;

    float* accs[2] = {acc0, acc1};
    #pragma unroll
    for (int half = 0; half < 2; ++half) {
        const float* d = accs[half];
        const int colg = n0 + nw * 16 + half * 8 + c0;

        const float* gp = g_gp + (size_t)(colg >> 1) * 20;
        float4 p0 = *(const float4*)(gp + 0);
        float4 p1 = *(const float4*)(gp + 4);
        float4 p2 = *(const float4*)(gp + 8);
        float4 p3 = *(const float4*)(gp + 12);
        float4 p4 = *(const float4*)(gp + 16);
        float cc[2][3]  = {{p0.x, p0.y, p0.z}, {p2.z, p2.w, p3.x}};
        float bb2[2]    = {p0.w, p3.y};
        float iv[2][3]  = {{p1.x, p1.y, p1.z}, {p3.z, p3.w, p4.x}};
        float qq[2][3]  = {{p1.w, p2.x, p2.y}, {p4.y, p4.z, p4.w}};

        #pragma unroll
        for (int p = 0; p < 2; ++p) {
            const int rl = rl0 + p * 8;
            const int rg = m0 + rl;
            float2 xv = *(const float2*)&xwt[(size_t)rg * HH + colg];
            __nv_bfloat162 hhi = *(const __nv_bfloat162*)(sAh + rl * SA_PITCH + colg);
            __nv_bfloat162 hlo = *(const __nv_bfloat162*)(sAl + rl * SA_PITCH + colg);
            float hin[2] = {__low2float(hhi) + __low2float(hlo),
                            __high2float(hhi) + __high2float(hlo)};
            float zz[2] = {d[2 * p + 0] + xv.x, d[2 * p + 1] + xv.y};
            float xa[2] = {xv.x, xv.y};
            float hn[2];
            #pragma unroll
            for (int j = 0; j < 2; ++j) {
                float z  = zz[j] + bb2[j];
                float d0 = z - cc[j][0], d1 = z - cc[j][1], d2 = z - cc[j][2];
                float mu0 = __expf(-d0 * d0 * iv[j][0]);
                float mu1 = __expf(-d1 * d1 * iv[j][1]);
                float mu2 = __expf(-d2 * d2 * iv[j][2]);
                float num = mu0 * qq[j][0] + mu1 * qq[j][1] + mu2 * qq[j][2];
                float den = mu0 + mu1 + mu2 + 1e-8f;
                float g   = 1.0f / (1.0f + __expf(-num / den));
                float ex  = __expf(-2.0f * xa[j]);
                float ni  = (1.0f - ex) / (1.0f + ex);
                hn[j] = (1.0f - g) * hin[j] + g * ni;
            }
            __nv_bfloat16 h0i = __float2bfloat16_rn(hn[0]);
            __nv_bfloat16 h1i = __float2bfloat16_rn(hn[1]);
            float l0 = hn[0] - __bfloat162float(h0i);
            float l1 = hn[1] - __bfloat162float(h1i);
            __nv_bfloat162 hiv; hiv.x = h0i; hiv.y = h1i;
            __nv_bfloat162 lov; lov.x = __float2bfloat16_rn(l0);
            lov.y = __float2bfloat16_rn(l1);
            *(__nv_bfloat162*)&hhn[(size_t)rg * HH + colg] = hiv;
            *(__nv_bfloat162*)&hln[(size_t)rg * HH + colg] = lov;
        }
    }
}

// ------------------------------------------------------------------
// Final: logits[b] = h_final[b] . Wc + bc
// ------------------------------------------------------------------
__global__ void __launch_bounds__(256) final_kernel(const float* __restrict__ Wc,
                                                    const float* __restrict__ bc,
                                                    float* __restrict__ out)
{
    const int warp = threadIdx.x >> 5;
    const int lane = threadIdx.x & 31;
    const int b = blockIdx.x * 8 + warp;
    const __nv_bfloat16* hhr = g_hh[0] + (size_t)b * HH;
    const __nv_bfloat16* hlr = g_hl[0] + (size_t)b * HH;
    float s = 0.0f;
    #pragma unroll
    for (int i = 0; i < 4; ++i) {
        int h = i * 128 + lane * 4;
        __nv_bfloat162 a0 = *(const __nv_bfloat162*)(hhr + h);
        __nv_bfloat162 a1 = *(const __nv_bfloat162*)(hhr + h + 2);
        __nv_bfloat162 l0 = *(const __nv_bfloat162*)(hlr + h);
        __nv_bfloat162 l1 = *(const __nv_bfloat162*)(hlr + h + 2);
        float4 w4 = *(const float4*)&Wc[h];
        s += (__low2float(a0)  + __low2float(l0))  * w4.x;
        s += (__high2float(a0) + __high2float(l0)) * w4.y;
        s += (__low2float(a1)  + __low2float(l1))  * w4.z;
        s += (__high2float(a1) + __high2float(l1)) * w4.w;
    }
    #pragma unroll
    for (int o = 16; o > 0; o >>= 1) s += __shfl_down_sync(0xffffffffu, s, o);
    if (lane == 0) out[b] = s + bc[0];
}

// ------------------------------------------------------------------
// Launch
// ------------------------------------------------------------------
extern "C" void kernel_launch(void* const* d_in, const int* in_sizes, int n_in,
                              void* d_out, int out_size)
{
    const float* x     = (const float*)d_in[0];
    const float* theta = (const float*)d_in[1];
    const float* Wx    = (const float*)d_in[2];
    const float* Wh    = (const float*)d_in[3];
    const float* bias  = (const float*)d_in[4];
    const float* c     = (const float*)d_in[5];
    const float* sigma = (const float*)d_in[6];
    const float* q     = (const float*)d_in[7];
    const float* Wc    = (const float*)d_in[8];
    const float* bc    = (const float*)d_in[9];
    float* out = (float*)d_out;

    static int configured = 0;
    if (!configured) {
        cudaFuncSetAttribute(step_kernel,
                             cudaFuncAttributeMaxDynamicSharedMemorySize,
                             SMEM_STEP_BYTES);
        cudaFuncSetAttribute(gemm1_hmma,
                             cudaFuncAttributeMaxDynamicSharedMemorySize,
                             SMEM_G1_BYTES);
        configured = 1;
    }

    prep_kernel<<<(BB * HH + 255) / 256, 256>>>(theta, Wx, Wh, sigma, c, q, bias, out);
    xcvt_kernel<<<(BB * TT * FF) / (256 * 4), 256>>>(x);
    gemm1_hmma<<<dim3((BB * TT) / 64, HH / 128), 256, SMEM_G1_BYTES>>>();
    for (int t = 0; t < TT; ++t)
        step_kernel<<<dim3(16, 8), 256, SMEM_STEP_BYTES>>>(t);
    final_kernel<<<64, 256>>>(Wc, bc, out);
}